// round 5
// baseline (speedup 1.0000x reference)
#include <cuda_runtime.h>
#include <cstdint>
#include <cstddef>

// ---------------------------------------------------------------------------
// Collapsed HybridKernelTransformer (x dead, S==1, h0=[1,2,1,2,...]).
// Two kernels per block (no serial prep kernels — every CTA redundantly
// derives the LN stats / proj / m4 / r-slice it needs, in fixed order so all
// CTAs agree bitwise):
//   attn: g_bufA[e] = hn[e] + Wo[i][e,:] . v      (streams Wo: 4MB DRAM)
//         hn = LN(g_bufB; ln2[i-1]) (or h0), v rebuilt per-thread from Wv (L2)
//   ff  : g_bufB[e] = hn1[e] + W2[i][e,:] . r     (streams W2: 16MB DRAM)
//         hn1 = LN(g_bufA; ln1[i]), r values rebuilt per-thread from W1 (L2)
// Tail: y_kernel (per-CTA final LN + Wc matvec), bcast to 4096 rows.
// ---------------------------------------------------------------------------

#define E    1024
#define FF   4096
#define NBLK 6

__device__ __align__(16) float g_bufA[E];  // pre-ln1
__device__ __align__(16) float g_bufB[E];  // pre-ln2
__device__ __align__(16) float g_y[1000];

// Deterministic 256-thread stats over a 1024-float global vector.
// Fixed reduction order; every CTA gets bitwise-identical mean/inv_std.
__device__ __forceinline__ void cta_stats(const float* __restrict__ v,
                                          float* s_mi, double* s_red, int tid)
{
    int lane = tid & 31, warp = tid >> 5;
    double s = 0.0, q = 0.0;
    #pragma unroll
    for (int k = 0; k < 4; k++) {
        double x = (double)v[tid * 4 + k];
        s += x; q += x * x;
    }
    #pragma unroll
    for (int o = 16; o; o >>= 1) {
        s += __shfl_xor_sync(0xffffffffu, s, o);
        q += __shfl_xor_sync(0xffffffffu, q, o);
    }
    if (lane == 0) { s_red[warp * 2] = s; s_red[warp * 2 + 1] = q; }
    __syncthreads();
    if (tid == 0) {
        double ss = 0.0, qq = 0.0;
        #pragma unroll
        for (int w = 0; w < 8; w++) { ss += s_red[w * 2]; qq += s_red[w * 2 + 1]; }
        double m   = ss * (1.0 / 1024.0);
        double var = qq * (1.0 / 1024.0) - m * m;
        s_mi[0] = (float)m;
        s_mi[1] = (float)rsqrt(var + 1e-5);
    }
    __syncthreads();
}

// ------------------------- attn: stream Wo ----------------------------------
// grid 512, block 256: CTA b owns rows e0=2b, e0+1.
__global__ void __launch_bounds__(256)
attn_kernel(int blk,
            const float* __restrict__ Wo,    // (6, E, E)
            const float* __restrict__ Wv,    // (6, E, 8)
            const float* __restrict__ phiq,  // (6, 8)
            const float* __restrict__ ln2g,  // (6, E)
            const float* __restrict__ ln2b)
{
    __shared__ float  s_mi[2];
    __shared__ double s_red[16];
    __shared__ float  sred0[8], sred1[8];
    int tid = threadIdx.x;
    int e0 = blockIdx.x * 2;

    // Issue DRAM weight loads first (front-batched; hides stats latency).
    const float4* r0 = (const float4*)(Wo + (size_t)blk * E * E + (size_t)e0 * E);
    const float4* r1 = r0 + E / 4;
    float4 w0 = r0[tid];
    float4 w1 = r1[tid];

    // LN stats of previous output (skip for block 0 — h0 is constant).
    float mn = 0.0f, inv = 0.0f;
    if (blk > 0) {
        cta_stats(g_bufB, s_mi, s_red, tid);
        mn = s_mi[0]; inv = s_mi[1];
    }
    const float* gg = ln2g + (size_t)(blk - 1) * E;   // valid only if blk>0
    const float* bb = ln2b + (size_t)(blk - 1) * E;

    // proj[8] (redundant per thread; 8 cosf)
    float proj[8];
    #pragma unroll
    for (int w = 0; w < 8; w++) {
        float hw = (blk == 0) ? ((w & 1) ? 2.0f : 1.0f)
                              : (g_bufB[w] - mn) * inv * gg[w] + bb[w];
        proj[w] = cosf(hw + phiq[blk * 8 + w]);
    }

    // Rebuild own v chunk: vv = v[4*tid .. 4*tid+3], from Wv (L2-hot).
    const float4* Wv4 = (const float4*)(Wv + (size_t)blk * E * 8);
    float4 vv;
    {
        float vt[4];
        #pragma unroll
        for (int c = 0; c < 4; c++) {
            int e = 4 * tid + c;
            float4 a = Wv4[e * 2], b2 = Wv4[e * 2 + 1];
            vt[c] = a.x * proj[0] + a.y * proj[1] + a.z * proj[2] + a.w * proj[3]
                  + b2.x * proj[4] + b2.y * proj[5] + b2.z * proj[6] + b2.w * proj[7];
        }
        vv.x = vt[0]; vv.y = vt[1]; vv.z = vt[2]; vv.w = vt[3];
    }

    float acc0 = w0.x * vv.x + w0.y * vv.y + w0.z * vv.z + w0.w * vv.w;
    float acc1 = w1.x * vv.x + w1.y * vv.y + w1.z * vv.z + w1.w * vv.w;

    #pragma unroll
    for (int o = 16; o; o >>= 1) {
        acc0 += __shfl_xor_sync(0xffffffffu, acc0, o);
        acc1 += __shfl_xor_sync(0xffffffffu, acc1, o);
    }
    int warp = tid >> 5, lane = tid & 31;
    if (lane == 0) { sred0[warp] = acc0; sred1[warp] = acc1; }
    __syncthreads();
    if (tid < 2) {
        int e = e0 + tid;
        float hn = (blk == 0) ? ((e & 1) ? 2.0f : 1.0f)
                              : (g_bufB[e] - mn) * inv * gg[e] + bb[e];
        const float* sr = tid ? sred1 : sred0;
        float s = 0.0f;
        #pragma unroll
        for (int w = 0; w < 8; w++) s += sr[w];
        g_bufA[e] = hn + s;
    }
}

// ------------------------- ff: stream W2 ------------------------------------
// grid 512, block 256: CTA b owns rows e0=2b, e0+1.
// Each thread rebuilds the 16 r-values its dot needs from W1 (L2-hot).
__global__ void __launch_bounds__(256)
ff_kernel(int blk,
          const float* __restrict__ W2,    // (6, E, FF)
          const float* __restrict__ W1,    // (6, FF, 4)
          const float* __restrict__ phif,  // (6, 4)
          const float* __restrict__ ln1g,
          const float* __restrict__ ln1b)
{
    __shared__ float  s_mi[2];
    __shared__ double s_red[16];
    __shared__ float  sred0[8], sred1[8];
    int tid = threadIdx.x;
    int e0 = blockIdx.x * 2;

    // Front-batch the 8 DRAM weight loads.
    const float4* r0 = (const float4*)(W2 + (size_t)blk * E * FF + (size_t)e0 * FF);
    const float4* r1 = r0 + FF / 4;
    float4 w0[4], w1[4];
    #pragma unroll
    for (int k = 0; k < 4; k++) {
        w0[k] = r0[tid + 256 * k];
        w1[k] = r1[tid + 256 * k];
    }

    // LN1 stats of g_bufA (hidden under the DRAM loads above).
    cta_stats(g_bufA, s_mi, s_red, tid);
    float mn = s_mi[0], inv = s_mi[1];
    const float* gg = ln1g + (size_t)blk * E;
    const float* bb = ln1b + (size_t)blk * E;

    float m4[4];
    #pragma unroll
    for (int w = 0; w < 4; w++) {
        float hn1w = (g_bufA[w] - mn) * inv * gg[w] + bb[w];
        m4[w] = cosf(hn1w) * cosf(phif[blk * 4 + w]);
    }

    const float4* W14 = (const float4*)(W1 + (size_t)blk * FF * 4);
    float acc0 = 0.0f, acc1 = 0.0f;
    #pragma unroll
    for (int k = 0; k < 4; k++) {
        int j = tid + 256 * k;         // float4 index within the W2 row
        float4 a = W14[4 * j + 0];
        float4 b2 = W14[4 * j + 1];
        float4 c = W14[4 * j + 2];
        float4 d = W14[4 * j + 3];
        float rv0 = fmaxf(a.x * m4[0] + a.y * m4[1] + a.z * m4[2] + a.w * m4[3], 0.0f);
        float rv1 = fmaxf(b2.x * m4[0] + b2.y * m4[1] + b2.z * m4[2] + b2.w * m4[3], 0.0f);
        float rv2 = fmaxf(c.x * m4[0] + c.y * m4[1] + c.z * m4[2] + c.w * m4[3], 0.0f);
        float rv3 = fmaxf(d.x * m4[0] + d.y * m4[1] + d.z * m4[2] + d.w * m4[3], 0.0f);
        acc0 += w0[k].x * rv0 + w0[k].y * rv1 + w0[k].z * rv2 + w0[k].w * rv3;
        acc1 += w1[k].x * rv0 + w1[k].y * rv1 + w1[k].z * rv2 + w1[k].w * rv3;
    }

    #pragma unroll
    for (int o = 16; o; o >>= 1) {
        acc0 += __shfl_xor_sync(0xffffffffu, acc0, o);
        acc1 += __shfl_xor_sync(0xffffffffu, acc1, o);
    }
    int warp = tid >> 5, lane = tid & 31;
    if (lane == 0) { sred0[warp] = acc0; sred1[warp] = acc1; }
    __syncthreads();
    if (tid < 2) {
        int e = e0 + tid;
        float hn1 = (g_bufA[e] - mn) * inv * gg[e] + bb[e];
        const float* sr = tid ? sred1 : sred0;
        float s = 0.0f;
        #pragma unroll
        for (int w = 0; w < 8; w++) s += sr[w];
        g_bufB[e] = hn1 + s;
    }
}

// ------------------------- classifier head ----------------------------------
// grid 500, block 256: CTA b owns classes c0=2b, c0+1.
// Final LN computed per-CTA (redundant, deterministic).
__global__ void __launch_bounds__(256)
y_kernel(const float* __restrict__ Wc, const float* __restrict__ bc,
         const float* __restrict__ ln2g, const float* __restrict__ ln2b)
{
    __shared__ __align__(16) float sh[E];
    __shared__ float  s_mi[2];
    __shared__ double s_red[16];
    __shared__ float  sred0[8], sred1[8];
    int tid = threadIdx.x;
    int c0 = blockIdx.x * 2;

    // Front-batch the Wc loads.
    const float4* r0 = (const float4*)(Wc + (size_t)c0 * E);
    const float4* r1 = r0 + E / 4;
    float4 w0 = r0[tid];
    float4 w1 = r1[tid];

    cta_stats(g_bufB, s_mi, s_red, tid);
    float mn = s_mi[0], inv = s_mi[1];
    const float* gg = ln2g + (size_t)(NBLK - 1) * E;
    const float* bb = ln2b + (size_t)(NBLK - 1) * E;
    #pragma unroll
    for (int k = 0; k < 4; k++) {
        int e = tid * 4 + k;
        sh[e] = (g_bufB[e] - mn) * inv * gg[e] + bb[e];
    }
    __syncthreads();

    const float4* sh4 = (const float4*)sh;
    float4 hh = sh4[tid];
    float acc0 = w0.x * hh.x + w0.y * hh.y + w0.z * hh.z + w0.w * hh.w;
    float acc1 = w1.x * hh.x + w1.y * hh.y + w1.z * hh.z + w1.w * hh.w;

    #pragma unroll
    for (int o = 16; o; o >>= 1) {
        acc0 += __shfl_xor_sync(0xffffffffu, acc0, o);
        acc1 += __shfl_xor_sync(0xffffffffu, acc1, o);
    }
    int warp = tid >> 5, lane = tid & 31;
    if (lane == 0) { sred0[warp] = acc0; sred1[warp] = acc1; }
    __syncthreads();
    if (tid < 2) {
        int c = c0 + tid;
        const float* sr = tid ? sred1 : sred0;
        float s = 0.0f;
        #pragma unroll
        for (int w = 0; w < 8; w++) s += sr[w];
        g_y[c] = s + bc[c];
    }
}

// ------------------------- broadcast ----------------------------------------
__global__ void __launch_bounds__(256)
bcast_kernel(float* __restrict__ out)
{
    __shared__ __align__(16) float4 sy[250];
    int tid = threadIdx.x;
    if (tid < 250) sy[tid] = ((const float4*)g_y)[tid];
    __syncthreads();
    int base = blockIdx.x * 8;
    #pragma unroll
    for (int r = 0; r < 8; r++) {
        if (tid < 250)
            ((float4*)(out + (size_t)(base + r) * 1000))[tid] = sy[tid];
    }
}

// ---------------------------------------------------------------------------
extern "C" void kernel_launch(void* const* d_in, const int* in_sizes, int n_in,
                              void* d_out, int out_size)
{
    // metadata order: x, Wq, Wk, Wv, Wo, phi_q, W1, W2, phi_f,
    //                 ln1_g, ln1_b, ln2_g, ln2_b, Wc, bc
    const float* Wv   = (const float*)d_in[3];
    const float* Wo   = (const float*)d_in[4];
    const float* phiq = (const float*)d_in[5];
    const float* W1   = (const float*)d_in[6];
    const float* W2   = (const float*)d_in[7];
    const float* phif = (const float*)d_in[8];
    const float* ln1g = (const float*)d_in[9];
    const float* ln1b = (const float*)d_in[10];
    const float* ln2g = (const float*)d_in[11];
    const float* ln2b = (const float*)d_in[12];
    const float* Wc   = (const float*)d_in[13];
    const float* bc   = (const float*)d_in[14];
    float* out = (float*)d_out;

    for (int i = 0; i < NBLK; i++) {
        attn_kernel<<<512, 256>>>(i, Wo, Wv, phiq, ln2g, ln2b);
        ff_kernel<<<512, 256>>>(i, W2, W1, phif, ln1g, ln1b);
    }
    y_kernel<<<500, 256>>>(Wc, bc, ln2g, ln2b);
    bcast_kernel<<<512, 256>>>(out);
}